// round 9
// baseline (speedup 1.0000x reference)
#include <cuda_runtime.h>
#include <cuda_bf16.h>
#include <math.h>

#define N      8192
#define NFEAT  256
#define NHID   64
#define NHEADS 4
#define NCLASS 121
#define DCAT   256   // NHEADS*NHID
#define CAP    768   // max neighbors per row (mean ~82, sigma ~9)

// ---------------- scratch (static __device__, no allocs) ----------------
__device__ __align__(16) __nv_bfloat16 g_Whb[(size_t)N * DCAT];  // layer1 Wh (bf16 gather operand)
__device__ __align__(16) float g_f1s[(size_t)N * NHEADS];  // f_src layer1, [row][head]
__device__ __align__(16) float g_f1d[(size_t)N * NHEADS];  // f_dst layer1, [row][head]
__device__ __align__(16) float g_h1[(size_t)N * DCAT];     // layer1 output (h_cat)
__device__ __align__(16) __nv_bfloat16 g_Wh2b[(size_t)N * 128];  // layer2 Wh (bf16, padded)
__device__ float g_fs2[N];
__device__ float g_fd2[N];
__device__ int   g_nbr[(size_t)N * CAP];                   // CSR neighbor lists (raw indices)
__device__ int   g_cnt[N];
__device__ __align__(16) float g_B2[256 * 128];            // packed+padded W_out [K][128]

// ---------------- weight prepack (layer2 only; layer1 reads Ws directly) ----------------
__global__ void pack_B2(const float* __restrict__ W_out) {
    int idx = blockIdx.x * blockDim.x + threadIdx.x;      // 32768
    int k = idx >> 7, n = idx & 127;
    g_B2[idx] = (n < NCLASS) ? W_out[(size_t)k * NCLASS + n] : 0.f;
}

// ---------------- shared-memory union for the mega kernel ----------------
union __align__(16) MegaSmem {
    struct { float As[64][33]; float Bs[32][128]; } g;   // GEMM path
    int wcnt[8];                                         // CSR path
};

// ================= MEGA kernel: GEMM1+f1 (blocks 0..255) || CSR build (256..8447) ========
__global__ void __launch_bounds__(256) k_mega1(const float* __restrict__ x,
                                               const float* __restrict__ Ws,
                                               const float* __restrict__ a_heads,
                                               const float* __restrict__ adj) {
    __shared__ MegaSmem su;
    const int bid = blockIdx.x;
    const int t = threadIdx.x;
    const int lane = t & 31, warp = t >> 5;

    if (bid < 256) {
        // ---------------- GEMM1: Whb[row,:] = x @ B1, plus f1 epilogue ----------------
        float (*As)[33]  = su.g.As;
        float (*Bs)[128] = su.g.Bs;
        const int tx = t & 15, ty = t >> 4;
        const int row0 = (bid >> 1) * 64;
        const int n0   = (bid & 1) * 128;
        float acc[4][8] = {};

        for (int k0 = 0; k0 < 256; k0 += 32) {
            #pragma unroll
            for (int i = 0; i < 2; i++) {
                int f   = t + i * 256;
                int row = f >> 3, kq = f & 7;
                float4 a4 = *(const float4*)(x + (size_t)(row0 + row) * 256 + k0 + kq * 4);
                As[row][kq * 4 + 0] = a4.x;
                As[row][kq * 4 + 1] = a4.y;
                As[row][kq * 4 + 2] = a4.z;
                As[row][kq * 4 + 3] = a4.w;
            }
            // B tile directly from Ws: col n=h*64+c -> Ws[h][k][c]
            #pragma unroll
            for (int i = 0; i < 4; i++) {
                int f = t + i * 256;
                int k = f >> 5, nq = f & 31;
                int n = n0 + nq * 4;
                int h = n >> 6, c = n & 63;
                *(float4*)&Bs[k][nq * 4] =
                    *(const float4*)(Ws + ((size_t)h * 256 + (k0 + k)) * 64 + c);
            }
            __syncthreads();
            #pragma unroll
            for (int kk = 0; kk < 32; kk++) {
                float a[4];
                #pragma unroll
                for (int i = 0; i < 4; i++) a[i] = As[ty * 4 + i][kk];
                float4 b0 = *(const float4*)&Bs[kk][tx * 4];
                float4 b1 = *(const float4*)&Bs[kk][64 + tx * 4];
                float b[8] = {b0.x, b0.y, b0.z, b0.w, b1.x, b1.y, b1.z, b1.w};
                #pragma unroll
                for (int i = 0; i < 4; i++)
                    #pragma unroll
                    for (int j = 0; j < 8; j++)
                        acc[i][j] += a[i] * b[j];
            }
            __syncthreads();
        }

        const int ha = n0 >> 6;   // heads {ha, ha+1}
        float aAs[4], aAd[4], aBs[4], aBd[4];
        #pragma unroll
        for (int j = 0; j < 4; j++) {
            int lc = tx * 4 + j;
            aAs[j] = a_heads[ha * 128 + lc];
            aAd[j] = a_heads[ha * 128 + 64 + lc];
            aBs[j] = a_heads[(ha + 1) * 128 + lc];
            aBd[j] = a_heads[(ha + 1) * 128 + 64 + lc];
        }
        #pragma unroll
        for (int i = 0; i < 4; i++) {
            const int row = row0 + ty * 4 + i;
            __nv_bfloat162* d0 = (__nv_bfloat162*)(g_Whb + (size_t)row * DCAT + n0 + tx * 4);
            __nv_bfloat162* d1 = (__nv_bfloat162*)(g_Whb + (size_t)row * DCAT + n0 + 64 + tx * 4);
            d0[0] = __floats2bfloat162_rn(acc[i][0], acc[i][1]);
            d0[1] = __floats2bfloat162_rn(acc[i][2], acc[i][3]);
            d1[0] = __floats2bfloat162_rn(acc[i][4], acc[i][5]);
            d1[1] = __floats2bfloat162_rn(acc[i][6], acc[i][7]);
            float sA = 0.f, dA = 0.f, sB = 0.f, dB = 0.f;
            #pragma unroll
            for (int j = 0; j < 4; j++) {
                sA += acc[i][j] * aAs[j];
                dA += acc[i][j] * aAd[j];
                sB += acc[i][4 + j] * aBs[j];
                dB += acc[i][4 + j] * aBd[j];
            }
            #pragma unroll
            for (int o = 1; o < 16; o <<= 1) {
                sA += __shfl_xor_sync(~0u, sA, o);
                dA += __shfl_xor_sync(~0u, dA, o);
                sB += __shfl_xor_sync(~0u, sB, o);
                dB += __shfl_xor_sync(~0u, dB, o);
            }
            if (tx == 0) {
                g_f1s[row * 4 + ha]     = sA;
                g_f1d[row * 4 + ha]     = dA;
                g_f1s[row * 4 + ha + 1] = sB;
                g_f1d[row * 4 + ha + 1] = dB;
            }
        }
    } else {
        // ---------------- CSR build for row i (pure adj stream, MLP=8) ----------------
        const int i = bid - 256;
        const float4* arow4 = (const float4*)(adj + (size_t)i * N);
        unsigned nm = 0;
        #pragma unroll
        for (int it = 0; it < 8; it++) {
            float4 v = __ldcs(&arow4[it * 256 + t]);   // 8 independent loads
            unsigned pm = (v.x != 0.f ? 1u : 0u) | (v.y != 0.f ? 2u : 0u)
                        | (v.z != 0.f ? 4u : 0u) | (v.w != 0.f ? 8u : 0u);
            nm |= pm << (it * 4);
        }
        int c  = __popc(nm);
        int sc = c;
        #pragma unroll
        for (int o = 1; o < 32; o <<= 1) {
            int u = __shfl_up_sync(~0u, sc, o);
            if (lane >= o) sc += u;
        }
        if (lane == 31) su.wcnt[warp] = sc;
        __syncthreads();
        int base = sc - c, total = 0;
        #pragma unroll
        for (int k = 0; k < 8; k++) {
            int cc = su.wcnt[k];
            if (k < warp) base += cc;
            total += cc;
        }
        {   // bit p of nm -> element (p>>2)*1024 + t*4 + (p&3)
            unsigned w = nm;
            int pos = base;
            while (w) {
                int p = __ffs(w) - 1;
                w &= w - 1;
                if (pos < CAP)
                    g_nbr[(size_t)i * CAP + pos] = ((p >> 2) << 10) + t * 4 + (p & 3);
                pos++;
            }
        }
        if (t == 0) g_cnt[i] = min(total, CAP);
    }
}

// ---------------- K1b: layer1 attention + aggregation (reads CSR) ----------------
__global__ void __launch_bounds__(256) k1b_attn() {
    const int i = blockIdx.x;
    const int t = threadIdx.x;
    const int lane = t & 31, warp = t >> 5;

    __shared__ int    s_nbr[CAP];        // byte offsets into g_Whb (j*512)
    __shared__ float4 s_p4[CAP];
    __shared__ float  s_wred[8][NHEADS];
    __shared__ float  s_sum[NHEADS];
    __shared__ float4 s_lo[8][32];
    __shared__ float4 s_hi[8][32];

    const int nn = g_cnt[i];
    const int* nb = g_nbr + (size_t)i * CAP;
    for (int jl = t; jl < nn; jl += 256) s_nbr[jl] = nb[jl] << 9;
    __syncthreads();

    // ---- Phase B: p = exp(lrelu(fs+fd)) one pass (no max; |e| small for this data) ----
    const float4 fs4 = *(const float4*)(g_f1s + 4 * i);
    float sl[NHEADS] = {0.f, 0.f, 0.f, 0.f};
    for (int jl = t; jl < nn; jl += 256) {
        int jb = s_nbr[jl];
        const float4 fd = *(const float4*)((const char*)g_f1d + (jb >> 5));  // j*16 B
        float4 e;
        e.x = fs4.x + fd.x; e.x = e.x > 0.f ? e.x : 0.2f * e.x; e.x = __expf(e.x);
        e.y = fs4.y + fd.y; e.y = e.y > 0.f ? e.y : 0.2f * e.y; e.y = __expf(e.y);
        e.z = fs4.z + fd.z; e.z = e.z > 0.f ? e.z : 0.2f * e.z; e.z = __expf(e.z);
        e.w = fs4.w + fd.w; e.w = e.w > 0.f ? e.w : 0.2f * e.w; e.w = __expf(e.w);
        s_p4[jl] = e;
        sl[0] += e.x; sl[1] += e.y; sl[2] += e.z; sl[3] += e.w;
    }
    #pragma unroll
    for (int h = 0; h < NHEADS; h++)
        #pragma unroll
        for (int o = 16; o; o >>= 1)
            sl[h] += __shfl_xor_sync(~0u, sl[h], o);
    if (lane == 0)
        #pragma unroll
        for (int h = 0; h < NHEADS; h++) s_wred[warp][h] = sl[h];
    __syncthreads();
    if (t < NHEADS) {
        float s = 0.f;
        #pragma unroll
        for (int w2 = 0; w2 < 8; w2++) s += s_wred[w2][t];
        s_sum[t] = s;
    }
    __syncthreads();

    // ---- aggregation: 8 neighbor-groups x 32 threads; LDG.128 (8 dims/thread) ----
    const int d8 = t & 31, grp = t >> 5;
    const int h = d8 >> 3;                        // dims 8*d8..8*d8+7 share head
    const char* basep = (const char*)g_Whb + 16 * d8;
    float4 lo0 = {0,0,0,0}, hi0 = {0,0,0,0}, lo1 = {0,0,0,0}, hi1 = {0,0,0,0};
    {
        int jl = grp;
        for (; jl + 8 < nn; jl += 16) {
            float w0 = ((const float*)&s_p4[jl])[h];
            float w1 = ((const float*)&s_p4[jl + 8])[h];
            uint4 q0 = *(const uint4*)(basep + s_nbr[jl]);
            uint4 q1 = *(const uint4*)(basep + s_nbr[jl + 8]);
            float2 p00 = __bfloat1622float2(*(const __nv_bfloat162*)&q0.x);
            float2 p01 = __bfloat1622float2(*(const __nv_bfloat162*)&q0.y);
            float2 p02 = __bfloat1622float2(*(const __nv_bfloat162*)&q0.z);
            float2 p03 = __bfloat1622float2(*(const __nv_bfloat162*)&q0.w);
            float2 p10 = __bfloat1622float2(*(const __nv_bfloat162*)&q1.x);
            float2 p11 = __bfloat1622float2(*(const __nv_bfloat162*)&q1.y);
            float2 p12 = __bfloat1622float2(*(const __nv_bfloat162*)&q1.z);
            float2 p13 = __bfloat1622float2(*(const __nv_bfloat162*)&q1.w);
            lo0.x += w0 * p00.x; lo0.y += w0 * p00.y; lo0.z += w0 * p01.x; lo0.w += w0 * p01.y;
            hi0.x += w0 * p02.x; hi0.y += w0 * p02.y; hi0.z += w0 * p03.x; hi0.w += w0 * p03.y;
            lo1.x += w1 * p10.x; lo1.y += w1 * p10.y; lo1.z += w1 * p11.x; lo1.w += w1 * p11.y;
            hi1.x += w1 * p12.x; hi1.y += w1 * p12.y; hi1.z += w1 * p13.x; hi1.w += w1 * p13.y;
        }
        for (; jl < nn; jl += 8) {
            float w0 = ((const float*)&s_p4[jl])[h];
            uint4 q0 = *(const uint4*)(basep + s_nbr[jl]);
            float2 p00 = __bfloat1622float2(*(const __nv_bfloat162*)&q0.x);
            float2 p01 = __bfloat1622float2(*(const __nv_bfloat162*)&q0.y);
            float2 p02 = __bfloat1622float2(*(const __nv_bfloat162*)&q0.z);
            float2 p03 = __bfloat1622float2(*(const __nv_bfloat162*)&q0.w);
            lo0.x += w0 * p00.x; lo0.y += w0 * p00.y; lo0.z += w0 * p01.x; lo0.w += w0 * p01.y;
            hi0.x += w0 * p02.x; hi0.y += w0 * p02.y; hi0.z += w0 * p03.x; hi0.w += w0 * p03.y;
        }
    }
    s_lo[grp][d8] = make_float4(lo0.x + lo1.x, lo0.y + lo1.y, lo0.z + lo1.z, lo0.w + lo1.w);
    s_hi[grp][d8] = make_float4(hi0.x + hi1.x, hi0.y + hi1.y, hi0.z + hi1.z, hi0.w + hi1.w);
    __syncthreads();
    if (t < 32) {
        float4 vlo = {0,0,0,0}, vhi = {0,0,0,0};
        #pragma unroll
        for (int g = 0; g < 8; g++) {
            float4 a = s_lo[g][t], b = s_hi[g][t];
            vlo.x += a.x; vlo.y += a.y; vlo.z += a.z; vlo.w += a.w;
            vhi.x += b.x; vhi.y += b.y; vhi.z += b.z; vhi.w += b.w;
        }
        float inv = 1.f / s_sum[t >> 3];
        vlo.x *= inv; vlo.y *= inv; vlo.z *= inv; vlo.w *= inv;
        vhi.x *= inv; vhi.y *= inv; vhi.z *= inv; vhi.w *= inv;
        vlo.x = vlo.x > 0.f ? vlo.x : expm1f(vlo.x);
        vlo.y = vlo.y > 0.f ? vlo.y : expm1f(vlo.y);
        vlo.z = vlo.z > 0.f ? vlo.z : expm1f(vlo.z);
        vlo.w = vlo.w > 0.f ? vlo.w : expm1f(vlo.w);
        vhi.x = vhi.x > 0.f ? vhi.x : expm1f(vhi.x);
        vhi.y = vhi.y > 0.f ? vhi.y : expm1f(vhi.y);
        vhi.z = vhi.z > 0.f ? vhi.z : expm1f(vhi.z);
        vhi.w = vhi.w > 0.f ? vhi.w : expm1f(vhi.w);
        *(float4*)(g_h1 + (size_t)i * DCAT + 8 * t)     = vlo;
        *(float4*)(g_h1 + (size_t)i * DCAT + 8 * t + 4) = vhi;
    }
}

// ---------------- GEMM2 (layer2) + f2 epilogue ----------------
__global__ void __launch_bounds__(256) gemm2_fused(const float* __restrict__ avec) {
    __shared__ float As[64][33];
    __shared__ float Bs[32][128];
    const int t  = threadIdx.x;
    const int tx = t & 15, ty = t >> 4;
    const int row0 = blockIdx.x * 64;
    float acc[4][8] = {};

    for (int k0 = 0; k0 < 256; k0 += 32) {
        #pragma unroll
        for (int i = 0; i < 2; i++) {
            int f   = t + i * 256;
            int row = f >> 3, kq = f & 7;
            float4 a4 = *(const float4*)(g_h1 + (size_t)(row0 + row) * 256 + k0 + kq * 4);
            As[row][kq * 4 + 0] = a4.x;
            As[row][kq * 4 + 1] = a4.y;
            As[row][kq * 4 + 2] = a4.z;
            As[row][kq * 4 + 3] = a4.w;
        }
        #pragma unroll
        for (int i = 0; i < 4; i++) {
            int f = t + i * 256;
            int k = f >> 5, nq = f & 31;
            *(float4*)&Bs[k][nq * 4] =
                *(const float4*)(g_B2 + (size_t)(k0 + k) * 128 + nq * 4);
        }
        __syncthreads();
        #pragma unroll
        for (int kk = 0; kk < 32; kk++) {
            float a[4];
            #pragma unroll
            for (int i = 0; i < 4; i++) a[i] = As[ty * 4 + i][kk];
            float4 b0 = *(const float4*)&Bs[kk][tx * 4];
            float4 b1 = *(const float4*)&Bs[kk][64 + tx * 4];
            float b[8] = {b0.x, b0.y, b0.z, b0.w, b1.x, b1.y, b1.z, b1.w};
            #pragma unroll
            for (int i = 0; i < 4; i++)
                #pragma unroll
                for (int j = 0; j < 8; j++)
                    acc[i][j] += a[i] * b[j];
        }
        __syncthreads();
    }

    float as0[4], ad0[4], as1[4], ad1[4];
    #pragma unroll
    for (int j = 0; j < 4; j++) {
        int c0 = tx * 4 + j;
        int c1 = 64 + tx * 4 + j;
        as0[j] = avec[c0];
        ad0[j] = avec[NCLASS + c0];
        as1[j] = (c1 < NCLASS) ? avec[c1] : 0.f;
        ad1[j] = (c1 < NCLASS) ? avec[NCLASS + c1] : 0.f;
    }
    #pragma unroll
    for (int i = 0; i < 4; i++) {
        const int row = row0 + ty * 4 + i;
        __nv_bfloat162* e0 = (__nv_bfloat162*)(g_Wh2b + (size_t)row * 128 + tx * 4);
        __nv_bfloat162* e1 = (__nv_bfloat162*)(g_Wh2b + (size_t)row * 128 + 64 + tx * 4);
        e0[0] = __floats2bfloat162_rn(acc[i][0], acc[i][1]);
        e0[1] = __floats2bfloat162_rn(acc[i][2], acc[i][3]);
        e1[0] = __floats2bfloat162_rn(acc[i][4], acc[i][5]);
        e1[1] = __floats2bfloat162_rn(acc[i][6], acc[i][7]);
        float s = 0.f, d = 0.f;
        #pragma unroll
        for (int j = 0; j < 4; j++) {
            s += acc[i][j] * as0[j] + acc[i][4 + j] * as1[j];
            d += acc[i][j] * ad0[j] + acc[i][4 + j] * ad1[j];
        }
        #pragma unroll
        for (int o = 1; o < 16; o <<= 1) {
            s += __shfl_xor_sync(~0u, s, o);
            d += __shfl_xor_sync(~0u, d, o);
        }
        if (tx == 0) { g_fs2[row] = s; g_fd2[row] = d; }
    }
}

// ---------------- K3: output-layer attention (reuses CSR) ----------------
__global__ void __launch_bounds__(256) k3_attn(float* __restrict__ out) {
    const int i = blockIdx.x;
    const int t = threadIdx.x;
    const int lane = t & 31, warp = t >> 5;
    __shared__ int    s_nbr[CAP];      // byte offsets into g_Wh2b (j*256)
    __shared__ float  s_p[CAP];
    __shared__ float  s_red[8];
    __shared__ float  s_s;
    __shared__ float4 s_part[8][32];

    const int nn = g_cnt[i];
    const int* nb = g_nbr + (size_t)i * CAP;
    for (int jl = t; jl < nn; jl += 256) s_nbr[jl] = nb[jl] << 8;
    __syncthreads();

    const float fs = g_fs2[i];
    float sloc = 0.f;
    for (int jl = t; jl < nn; jl += 256) {
        int jb = s_nbr[jl];
        float fd = *(const float*)((const char*)g_fd2 + (jb >> 6));   // j*4 B
        float e = fs + fd;
        e = e > 0.f ? e : 0.2f * e;
        e = __expf(e);
        s_p[jl] = e;
        sloc += e;
    }
    #pragma unroll
    for (int o = 16; o; o >>= 1) sloc += __shfl_xor_sync(~0u, sloc, o);
    if (!lane) s_red[warp] = sloc;
    __syncthreads();
    if (t == 0) {
        float s = 0.f;
        #pragma unroll
        for (int w = 0; w < 8; w++) s += s_red[w];
        s_s = s;
    }
    __syncthreads();

    // gather: 8 neighbor-groups x 32 dim-quads; LDG.64 bf16x4
    const int d4 = t & 31, grp = t >> 5;
    const char* basep = (const char*)g_Wh2b + 8 * d4;
    float4 a0 = {0.f, 0.f, 0.f, 0.f}, a1 = {0.f, 0.f, 0.f, 0.f};
    {
        int jl = grp;
        for (; jl + 8 < nn; jl += 16) {
            float w0 = s_p[jl], w1 = s_p[jl + 8];
            uint2 q0 = *(const uint2*)(basep + s_nbr[jl]);
            uint2 q1 = *(const uint2*)(basep + s_nbr[jl + 8]);
            float2 l0 = __bfloat1622float2(*(const __nv_bfloat162*)&q0.x);
            float2 h0 = __bfloat1622float2(*(const __nv_bfloat162*)&q0.y);
            float2 l1 = __bfloat1622float2(*(const __nv_bfloat162*)&q1.x);
            float2 h1 = __bfloat1622float2(*(const __nv_bfloat162*)&q1.y);
            a0.x += w0 * l0.x; a0.y += w0 * l0.y; a0.z += w0 * h0.x; a0.w += w0 * h0.y;
            a1.x += w1 * l1.x; a1.y += w1 * l1.y; a1.z += w1 * h1.x; a1.w += w1 * h1.y;
        }
        for (; jl < nn; jl += 8) {
            float w0 = s_p[jl];
            uint2 q0 = *(const uint2*)(basep + s_nbr[jl]);
            float2 l0 = __bfloat1622float2(*(const __nv_bfloat162*)&q0.x);
            float2 h0 = __bfloat1622float2(*(const __nv_bfloat162*)&q0.y);
            a0.x += w0 * l0.x; a0.y += w0 * l0.y; a0.z += w0 * h0.x; a0.w += w0 * h0.y;
        }
    }
    s_part[grp][d4] = make_float4(a0.x + a1.x, a0.y + a1.y, a0.z + a1.z, a0.w + a1.w);
    __syncthreads();
    if (t < 32) {
        float4 v = {0.f, 0.f, 0.f, 0.f};
        #pragma unroll
        for (int g = 0; g < 8; g++) {
            float4 r = s_part[g][t];
            v.x += r.x; v.y += r.y; v.z += r.z; v.w += r.w;
        }
        float inv = 1.f / s_s;
        int c0 = 4 * t;
        if (c0 + 0 < NCLASS) out[(size_t)i * NCLASS + c0 + 0] = v.x * inv;
        if (c0 + 1 < NCLASS) out[(size_t)i * NCLASS + c0 + 1] = v.y * inv;
        if (c0 + 2 < NCLASS) out[(size_t)i * NCLASS + c0 + 2] = v.z * inv;
        if (c0 + 3 < NCLASS) out[(size_t)i * NCLASS + c0 + 3] = v.w * inv;
    }
}

// ---------------- launcher ----------------
extern "C" void kernel_launch(void* const* d_in, const int* in_sizes, int n_in,
                              void* d_out, int out_size) {
    const float* x       = (const float*)d_in[0];
    const float* adj     = (const float*)d_in[1];
    const float* Ws      = (const float*)d_in[2];
    const float* a_heads = (const float*)d_in[3];
    const float* W_out   = (const float*)d_in[4];
    const float* a_out   = (const float*)d_in[5];
    float* out = (float*)d_out;

    pack_B2<<<128, 256>>>(W_out);
    k_mega1<<<256 + N, 256>>>(x, Ws, a_heads, adj);   // GEMM1+f1 || CSR build
    k1b_attn<<<N, 256>>>();
    gemm2_fused<<<N / 64, 256>>>(a_out);
    k3_attn<<<N, 256>>>(out);
}

// round 10
// speedup vs baseline: 1.0257x; 1.0257x over previous
#include <cuda_runtime.h>
#include <cuda_bf16.h>
#include <math.h>

#define N      8192
#define NFEAT  256
#define NHID   64
#define NHEADS 4
#define NCLASS 121
#define DCAT   256   // NHEADS*NHID
#define CAP    768   // max neighbors per row (mean ~82, sigma ~9)

// ---------------- scratch (static __device__, no allocs) ----------------
__device__ __align__(16) __nv_bfloat16 g_Whb[(size_t)N * DCAT];  // layer1 Wh (bf16 gather operand)
__device__ __align__(16) float g_f1s[(size_t)N * NHEADS];  // f_src layer1, [row][head]
__device__ __align__(16) float g_f1d[(size_t)N * NHEADS];  // f_dst layer1, [row][head]
__device__ __align__(16) float g_h1[(size_t)N * DCAT];     // layer1 output (h_cat)
__device__ __align__(16) __nv_bfloat16 g_Wh2b[(size_t)N * 128];  // layer2 Wh (bf16, padded)
__device__ float g_fs2[N];
__device__ float g_fd2[N];
__device__ int   g_nbr[(size_t)N * CAP];                   // CSR neighbor lists (raw indices)
__device__ int   g_cnt[N];
__device__ __align__(16) float g_B2[256 * 128];            // packed+padded W_out [K][128]

// ---------------- weight prepack (layer2 only; layer1 reads Ws directly) ----------------
__global__ void pack_B2(const float* __restrict__ W_out) {
    int idx = blockIdx.x * blockDim.x + threadIdx.x;      // 32768
    int k = idx >> 7, n = idx & 127;
    g_B2[idx] = (n < NCLASS) ? W_out[(size_t)k * NCLASS + n] : 0.f;
}

// ---------------- fused GEMM + f-score epilogue: 32x128 tile, 2x8 micro-tile ----------------
// 256 threads: tx=t&15 (col pair {tx*4.., 64+tx*4..}), ty=t>>4 (rows ty*2, ty*2+1).
// MODE 1: A=x, B read directly from Ws (head-indexed); writes g_Whb (bf16) + f1s/f1d.
// MODE 2: A=g_h1, B=g_B2; writes g_Wh2b (bf16) + fs2/fd2.
template <int MODE>
__global__ void __launch_bounds__(256) gemm_fused(const float* __restrict__ A,
                                                  const float* __restrict__ Wsrc,
                                                  const float* __restrict__ avec) {
    __shared__ float As[32][33];
    __shared__ float Bs[32][128];
    const int t  = threadIdx.x;
    const int tx = t & 15, ty = t >> 4;
    const int row0 = blockIdx.x * 32;
    const int n0   = (MODE == 1) ? blockIdx.y * 128 : 0;
    float acc[2][8] = {};

    for (int k0 = 0; k0 < 256; k0 += 32) {
        // A tile: 32x32 = 256 float4, 1 per thread
        {
            int row = t >> 3, kq = t & 7;
            float4 a4 = *(const float4*)(A + (size_t)(row0 + row) * 256 + k0 + kq * 4);
            As[row][kq * 4 + 0] = a4.x;
            As[row][kq * 4 + 1] = a4.y;
            As[row][kq * 4 + 2] = a4.z;
            As[row][kq * 4 + 3] = a4.w;
        }
        // B tile: 32x128 = 1024 float4, 4 per thread
        #pragma unroll
        for (int i = 0; i < 4; i++) {
            int f = t + i * 256;
            int k = f >> 5, nq = f & 31;
            if (MODE == 1) {
                int n = n0 + nq * 4;
                int h = n >> 6, c = n & 63;
                *(float4*)&Bs[k][nq * 4] =
                    *(const float4*)(Wsrc + ((size_t)h * 256 + (k0 + k)) * 64 + c);
            } else {
                *(float4*)&Bs[k][nq * 4] =
                    *(const float4*)(Wsrc + (size_t)(k0 + k) * 128 + nq * 4);
            }
        }
        __syncthreads();
        #pragma unroll
        for (int kk = 0; kk < 32; kk++) {
            float a0 = As[ty * 2][kk], a1 = As[ty * 2 + 1][kk];
            float4 b0 = *(const float4*)&Bs[kk][tx * 4];
            float4 b1 = *(const float4*)&Bs[kk][64 + tx * 4];
            float b[8] = {b0.x, b0.y, b0.z, b0.w, b1.x, b1.y, b1.z, b1.w};
            #pragma unroll
            for (int j = 0; j < 8; j++) {
                acc[0][j] += a0 * b[j];
                acc[1][j] += a1 * b[j];
            }
        }
        __syncthreads();
    }

    if (MODE == 1) {
        const int ha = n0 >> 6;   // heads {ha, ha+1}
        float aAs[4], aAd[4], aBs[4], aBd[4];
        #pragma unroll
        for (int j = 0; j < 4; j++) {
            int lc = tx * 4 + j;
            aAs[j] = avec[ha * 128 + lc];
            aAd[j] = avec[ha * 128 + 64 + lc];
            aBs[j] = avec[(ha + 1) * 128 + lc];
            aBd[j] = avec[(ha + 1) * 128 + 64 + lc];
        }
        #pragma unroll
        for (int i = 0; i < 2; i++) {
            const int row = row0 + ty * 2 + i;
            __nv_bfloat162* d0 = (__nv_bfloat162*)(g_Whb + (size_t)row * DCAT + n0 + tx * 4);
            __nv_bfloat162* d1 = (__nv_bfloat162*)(g_Whb + (size_t)row * DCAT + n0 + 64 + tx * 4);
            d0[0] = __floats2bfloat162_rn(acc[i][0], acc[i][1]);
            d0[1] = __floats2bfloat162_rn(acc[i][2], acc[i][3]);
            d1[0] = __floats2bfloat162_rn(acc[i][4], acc[i][5]);
            d1[1] = __floats2bfloat162_rn(acc[i][6], acc[i][7]);
            float sA = 0.f, dA = 0.f, sB = 0.f, dB = 0.f;
            #pragma unroll
            for (int j = 0; j < 4; j++) {
                sA += acc[i][j] * aAs[j];
                dA += acc[i][j] * aAd[j];
                sB += acc[i][4 + j] * aBs[j];
                dB += acc[i][4 + j] * aBd[j];
            }
            #pragma unroll
            for (int o = 1; o < 16; o <<= 1) {
                sA += __shfl_xor_sync(~0u, sA, o);
                dA += __shfl_xor_sync(~0u, dA, o);
                sB += __shfl_xor_sync(~0u, sB, o);
                dB += __shfl_xor_sync(~0u, dB, o);
            }
            if (tx == 0) {
                g_f1s[row * 4 + ha]     = sA;
                g_f1d[row * 4 + ha]     = dA;
                g_f1s[row * 4 + ha + 1] = sB;
                g_f1d[row * 4 + ha + 1] = dB;
            }
        }
    } else {
        float as0[4], ad0[4], as1[4], ad1[4];
        #pragma unroll
        for (int j = 0; j < 4; j++) {
            int c0 = tx * 4 + j;
            int c1 = 64 + tx * 4 + j;
            as0[j] = avec[c0];
            ad0[j] = avec[NCLASS + c0];
            as1[j] = (c1 < NCLASS) ? avec[c1] : 0.f;
            ad1[j] = (c1 < NCLASS) ? avec[NCLASS + c1] : 0.f;
        }
        #pragma unroll
        for (int i = 0; i < 2; i++) {
            const int row = row0 + ty * 2 + i;
            __nv_bfloat162* e0 = (__nv_bfloat162*)(g_Wh2b + (size_t)row * 128 + tx * 4);
            __nv_bfloat162* e1 = (__nv_bfloat162*)(g_Wh2b + (size_t)row * 128 + 64 + tx * 4);
            e0[0] = __floats2bfloat162_rn(acc[i][0], acc[i][1]);
            e0[1] = __floats2bfloat162_rn(acc[i][2], acc[i][3]);
            e1[0] = __floats2bfloat162_rn(acc[i][4], acc[i][5]);
            e1[1] = __floats2bfloat162_rn(acc[i][6], acc[i][7]);
            float s = 0.f, d = 0.f;
            #pragma unroll
            for (int j = 0; j < 4; j++) {
                s += acc[i][j] * as0[j] + acc[i][4 + j] * as1[j];
                d += acc[i][j] * ad0[j] + acc[i][4 + j] * ad1[j];
            }
            #pragma unroll
            for (int o = 1; o < 16; o <<= 1) {
                s += __shfl_xor_sync(~0u, s, o);
                d += __shfl_xor_sync(~0u, d, o);
            }
            if (tx == 0) { g_fs2[row] = s; g_fd2[row] = d; }
        }
    }
}

// ---------------- K1: layer1 sparse attention + aggregation (1 block / row) ----------------
// Phase A: 8 independent LDG.128 -> per-thread nibble word (MLP=8). No-max softmax.
__global__ void __launch_bounds__(256) k1_attn(const float* __restrict__ adj) {
    const int i = blockIdx.x;
    const int t = threadIdx.x;
    const int lane = t & 31, warp = t >> 5;

    __shared__ int    s_nbr[CAP];        // byte offsets into g_Whb (j*512)
    __shared__ float4 s_p4[CAP];         // per-neighbor 4-head exp weights
    __shared__ int    s_wcnt[8];
    __shared__ float  s_wred[8][NHEADS];
    __shared__ float  s_sum[NHEADS];
    __shared__ float4 s_part[4][64];

    // ---- Phase A: stream adj row; thread t covers elements {it*1024 + t*4 + c} ----
    const float4* arow4 = (const float4*)(adj + (size_t)i * N);
    unsigned nm = 0;
    #pragma unroll
    for (int it = 0; it < 8; it++) {
        float4 v = __ldcs(&arow4[it * 256 + t]);   // independent addresses: full MLP
        unsigned pm = (v.x != 0.f ? 1u : 0u) | (v.y != 0.f ? 2u : 0u)
                    | (v.z != 0.f ? 4u : 0u) | (v.w != 0.f ? 8u : 0u);
        nm |= pm << (it * 4);
    }
    int c  = __popc(nm);
    int sc = c;
    #pragma unroll
    for (int o = 1; o < 32; o <<= 1) {
        int u = __shfl_up_sync(~0u, sc, o);
        if (lane >= o) sc += u;
    }
    if (lane == 31) s_wcnt[warp] = sc;
    __syncthreads();
    int base = sc - c, total = 0;
    #pragma unroll
    for (int k = 0; k < 8; k++) {
        int cc = s_wcnt[k];
        if (k < warp) base += cc;
        total += cc;
    }
    const int nn = min(total, CAP);
    {   // bit p of nm -> element (p>>2)*1024 + t*4 + (p&3)
        unsigned w = nm;
        int pos = base;
        while (w) {
            int p = __ffs(w) - 1;
            w &= w - 1;
            if (pos < CAP) {
                int j = ((p >> 2) << 10) + t * 4 + (p & 3);
                s_nbr[pos] = j << 9;               // byte offset: j * DCAT * 2
                g_nbr[(size_t)i * CAP + pos] = j;
            }
            pos++;
        }
    }
    if (t == 0) g_cnt[i] = nn;
    __syncthreads();

    // ---- Phase B: p = exp(lrelu(fs+fd)) one pass, accumulate sums ----
    const float4 fs4 = *(const float4*)(g_f1s + 4 * i);
    float sl[NHEADS] = {0.f, 0.f, 0.f, 0.f};
    for (int jl = t; jl < nn; jl += 256) {
        int jb = s_nbr[jl];
        const float4 fd = *(const float4*)((const char*)g_f1d + (jb >> 5));  // j*16 B
        float4 e;
        e.x = fs4.x + fd.x; e.x = e.x > 0.f ? e.x : 0.2f * e.x; e.x = __expf(e.x);
        e.y = fs4.y + fd.y; e.y = e.y > 0.f ? e.y : 0.2f * e.y; e.y = __expf(e.y);
        e.z = fs4.z + fd.z; e.z = e.z > 0.f ? e.z : 0.2f * e.z; e.z = __expf(e.z);
        e.w = fs4.w + fd.w; e.w = e.w > 0.f ? e.w : 0.2f * e.w; e.w = __expf(e.w);
        s_p4[jl] = e;
        sl[0] += e.x; sl[1] += e.y; sl[2] += e.z; sl[3] += e.w;
    }
    #pragma unroll
    for (int h = 0; h < NHEADS; h++)
        #pragma unroll
        for (int o = 16; o; o >>= 1)
            sl[h] += __shfl_xor_sync(~0u, sl[h], o);
    if (lane == 0)
        #pragma unroll
        for (int h = 0; h < NHEADS; h++) s_wred[warp][h] = sl[h];
    __syncthreads();
    if (t < NHEADS) {
        float s = 0.f;
        #pragma unroll
        for (int w2 = 0; w2 < 8; w2++) s += s_wred[w2][t];
        s_sum[t] = s;
    }
    __syncthreads();

    // ---- aggregation: 4 neighbor-groups x 64 dim-quads; LDG.64 bf16x4 ----
    const int d4 = t & 63, grp = t >> 6;
    const int h = d4 >> 4;
    const char* basep = (const char*)g_Whb + 8 * d4;
    float4 a0 = {0.f, 0.f, 0.f, 0.f}, a1 = {0.f, 0.f, 0.f, 0.f};
    {
        int jl = grp;
        for (; jl + 4 < nn; jl += 8) {
            float w0 = ((const float*)&s_p4[jl])[h];
            float w1 = ((const float*)&s_p4[jl + 4])[h];
            uint2 q0 = *(const uint2*)(basep + s_nbr[jl]);
            uint2 q1 = *(const uint2*)(basep + s_nbr[jl + 4]);
            float2 l0 = __bfloat1622float2(*(const __nv_bfloat162*)&q0.x);
            float2 h0 = __bfloat1622float2(*(const __nv_bfloat162*)&q0.y);
            float2 l1 = __bfloat1622float2(*(const __nv_bfloat162*)&q1.x);
            float2 h1 = __bfloat1622float2(*(const __nv_bfloat162*)&q1.y);
            a0.x += w0 * l0.x; a0.y += w0 * l0.y; a0.z += w0 * h0.x; a0.w += w0 * h0.y;
            a1.x += w1 * l1.x; a1.y += w1 * l1.y; a1.z += w1 * h1.x; a1.w += w1 * h1.y;
        }
        for (; jl < nn; jl += 4) {
            float w0 = ((const float*)&s_p4[jl])[h];
            uint2 q0 = *(const uint2*)(basep + s_nbr[jl]);
            float2 l0 = __bfloat1622float2(*(const __nv_bfloat162*)&q0.x);
            float2 h0 = __bfloat1622float2(*(const __nv_bfloat162*)&q0.y);
            a0.x += w0 * l0.x; a0.y += w0 * l0.y; a0.z += w0 * h0.x; a0.w += w0 * h0.y;
        }
    }
    s_part[grp][d4] = make_float4(a0.x + a1.x, a0.y + a1.y, a0.z + a1.z, a0.w + a1.w);
    __syncthreads();
    if (t < 64) {
        float4 r0 = s_part[0][t], r1 = s_part[1][t], r2 = s_part[2][t], r3 = s_part[3][t];
        float inv = 1.f / s_sum[t >> 4];
        float4 v;
        v.x = (r0.x + r1.x + r2.x + r3.x) * inv;
        v.y = (r0.y + r1.y + r2.y + r3.y) * inv;
        v.z = (r0.z + r1.z + r2.z + r3.z) * inv;
        v.w = (r0.w + r1.w + r2.w + r3.w) * inv;
        v.x = v.x > 0.f ? v.x : expm1f(v.x);
        v.y = v.y > 0.f ? v.y : expm1f(v.y);
        v.z = v.z > 0.f ? v.z : expm1f(v.z);
        v.w = v.w > 0.f ? v.w : expm1f(v.w);
        *(float4*)(g_h1 + (size_t)i * DCAT + 4 * t) = v;
    }
}

// ---------------- K3: output-layer attention (1 block / row, reuses CSR) ----------------
__global__ void __launch_bounds__(256) k3_attn(float* __restrict__ out) {
    const int i = blockIdx.x;
    const int t = threadIdx.x;
    const int lane = t & 31, warp = t >> 5;
    __shared__ int    s_nbr[CAP];      // byte offsets into g_Wh2b (j*256)
    __shared__ float  s_p[CAP];
    __shared__ float  s_red[8];
    __shared__ float  s_s;
    __shared__ float4 s_part[8][32];

    const int nn = g_cnt[i];
    const int* nb = g_nbr + (size_t)i * CAP;
    for (int jl = t; jl < nn; jl += 256) s_nbr[jl] = nb[jl] << 8;
    __syncthreads();

    const float fs = g_fs2[i];
    float sloc = 0.f;
    for (int jl = t; jl < nn; jl += 256) {
        int jb = s_nbr[jl];
        float fd = *(const float*)((const char*)g_fd2 + (jb >> 6));   // j*4 B
        float e = fs + fd;
        e = e > 0.f ? e : 0.2f * e;
        e = __expf(e);
        s_p[jl] = e;
        sloc += e;
    }
    #pragma unroll
    for (int o = 16; o; o >>= 1) sloc += __shfl_xor_sync(~0u, sloc, o);
    if (!lane) s_red[warp] = sloc;
    __syncthreads();
    if (t == 0) {
        float s = 0.f;
        #pragma unroll
        for (int w = 0; w < 8; w++) s += s_red[w];
        s_s = s;
    }
    __syncthreads();

    // gather: 8 neighbor-groups x 32 dim-quads; LDG.64 bf16x4
    const int d4 = t & 31, grp = t >> 5;
    const char* basep = (const char*)g_Wh2b + 8 * d4;
    float4 a0 = {0.f, 0.f, 0.f, 0.f}, a1 = {0.f, 0.f, 0.f, 0.f};
    {
        int jl = grp;
        for (; jl + 8 < nn; jl += 16) {
            float w0 = s_p[jl], w1 = s_p[jl + 8];
            uint2 q0 = *(const uint2*)(basep + s_nbr[jl]);
            uint2 q1 = *(const uint2*)(basep + s_nbr[jl + 8]);
            float2 l0 = __bfloat1622float2(*(const __nv_bfloat162*)&q0.x);
            float2 h0 = __bfloat1622float2(*(const __nv_bfloat162*)&q0.y);
            float2 l1 = __bfloat1622float2(*(const __nv_bfloat162*)&q1.x);
            float2 h1 = __bfloat1622float2(*(const __nv_bfloat162*)&q1.y);
            a0.x += w0 * l0.x; a0.y += w0 * l0.y; a0.z += w0 * h0.x; a0.w += w0 * h0.y;
            a1.x += w1 * l1.x; a1.y += w1 * l1.y; a1.z += w1 * h1.x; a1.w += w1 * h1.y;
        }
        for (; jl < nn; jl += 8) {
            float w0 = s_p[jl];
            uint2 q0 = *(const uint2*)(basep + s_nbr[jl]);
            float2 l0 = __bfloat1622float2(*(const __nv_bfloat162*)&q0.x);
            float2 h0 = __bfloat1622float2(*(const __nv_bfloat162*)&q0.y);
            a0.x += w0 * l0.x; a0.y += w0 * l0.y; a0.z += w0 * h0.x; a0.w += w0 * h0.y;
        }
    }
    s_part[grp][d4] = make_float4(a0.x + a1.x, a0.y + a1.y, a0.z + a1.z, a0.w + a1.w);
    __syncthreads();
    if (t < 32) {
        float4 v = {0.f, 0.f, 0.f, 0.f};
        #pragma unroll
        for (int g = 0; g < 8; g++) {
            float4 r = s_part[g][t];
            v.x += r.x; v.y += r.y; v.z += r.z; v.w += r.w;
        }
        float inv = 1.f / s_s;
        int c0 = 4 * t;
        if (c0 + 0 < NCLASS) out[(size_t)i * NCLASS + c0 + 0] = v.x * inv;
        if (c0 + 1 < NCLASS) out[(size_t)i * NCLASS + c0 + 1] = v.y * inv;
        if (c0 + 2 < NCLASS) out[(size_t)i * NCLASS + c0 + 2] = v.z * inv;
        if (c0 + 3 < NCLASS) out[(size_t)i * NCLASS + c0 + 3] = v.w * inv;
    }
}

// ---------------- launcher ----------------
extern "C" void kernel_launch(void* const* d_in, const int* in_sizes, int n_in,
                              void* d_out, int out_size) {
    const float* x       = (const float*)d_in[0];
    const float* adj     = (const float*)d_in[1];
    const float* Ws      = (const float*)d_in[2];
    const float* a_heads = (const float*)d_in[3];
    const float* W_out   = (const float*)d_in[4];
    const float* a_out   = (const float*)d_in[5];
    float* out = (float*)d_out;

    float* pB2;  cudaGetSymbolAddress((void**)&pB2, g_B2);
    float* pH1;  cudaGetSymbolAddress((void**)&pH1, g_h1);

    pack_B2<<<128, 256>>>(W_out);
    gemm_fused<1><<<dim3(N / 32, 2), 256>>>(x, Ws, a_heads);     // layer1 Wh + f1 (512 blocks)
    k1_attn<<<N, 256>>>(adj);
    gemm_fused<2><<<dim3(N / 32, 1), 256>>>(pH1, pB2, a_out);    // layer2 Wh + f2 (256 blocks)
    k3_attn<<<N, 256>>>(out);
}

// round 11
// speedup vs baseline: 1.1782x; 1.1486x over previous
#include <cuda_runtime.h>
#include <cuda_bf16.h>
#include <math.h>

#define N      8192
#define NFEAT  256
#define NHID   64
#define NHEADS 4
#define NCLASS 121
#define DCAT   256   // NHEADS*NHID
#define CAP    768   // max neighbors per row (mean ~82, sigma ~9)

// ---------------- scratch (static __device__, no allocs) ----------------
__device__ __align__(16) __nv_bfloat16 g_Whb[(size_t)N * DCAT];  // layer1 Wh (bf16 gather operand)
__device__ __align__(16) float g_f1s[(size_t)N * NHEADS];  // f_src layer1, [row][head]
__device__ __align__(16) float g_f1d[(size_t)N * NHEADS];  // f_dst layer1, [row][head]
__device__ __align__(16) float g_h1[(size_t)N * DCAT];     // layer1 output (h_cat)
__device__ __align__(16) __nv_bfloat16 g_Wh2b[(size_t)N * 128];  // layer2 Wh (bf16, padded)
__device__ float g_fs2[N];
__device__ float g_fd2[N];
__device__ int   g_nbr[(size_t)N * CAP];                   // CSR neighbor lists (raw indices)
__device__ int   g_cnt[N];
__device__ __align__(16) float g_B1[256 * 256];            // packed layer1 weights [K][DCAT]
__device__ __align__(16) float g_B2[256 * 128];            // packed+padded W_out   [K][128]

// ---------------- weight prepack ----------------
__global__ void pack_B1(const float* __restrict__ Ws) {
    int idx = blockIdx.x * blockDim.x + threadIdx.x;      // 65536
    int k = idx >> 8, n = idx & 255;
    int h = n >> 6, c = n & 63;
    g_B1[idx] = Ws[(size_t)h * NFEAT * NHID + (size_t)k * NHID + c];
}
__global__ void pack_B2(const float* __restrict__ W_out) {
    int idx = blockIdx.x * blockDim.x + threadIdx.x;      // 32768
    int k = idx >> 7, n = idx & 127;
    g_B2[idx] = (n < NCLASS) ? W_out[(size_t)k * NCLASS + n] : 0.f;
}

// ---------------- fused GEMM + f-score epilogue (64x128 tile, 4x8 micro) ----------------
// A-tile stored k-major (As[k][row]) -> compute reads are 3x LDS.128 per 32 FMA.
// Register-prefetch of next k-slab overlaps gmem latency with compute.
// MODE 1: store bf16 Wh to g_Whb, compute f1s/f1d (head-major) for 2 heads.
// MODE 2: store bf16 to g_Wh2b (zero-padded), compute g_fs2/g_fd2.
template <int MODE>
__global__ void __launch_bounds__(256) gemm_fused(const float* __restrict__ A,
                                                  const float* __restrict__ B, int ldb,
                                                  const float* __restrict__ avec) {
    __shared__ float As[32][68];    // [k][row], stride 68: LDS.128-aligned, bank-spread
    __shared__ float Bs[32][128];   // [k][n]
    const int t    = threadIdx.x;
    const int tx   = t & 15, ty = t >> 4;
    const int row0 = blockIdx.x * 64;
    const int n0   = blockIdx.y * 128;
    const int arow = t >> 3, akq = t & 7;          // A-load coords (row, k-quad)
    const int bk   = t >> 5, bnq = t & 31;         // B-load coords (k, n-quad) for i-th chunk
    float acc[4][8] = {};
    float4 pa[2], pb[4];

    // prologue: load k-slab 0
    #pragma unroll
    for (int i = 0; i < 2; i++)
        pa[i] = *(const float4*)(A + (size_t)(row0 + arow + i * 32) * 256 + akq * 4);
    #pragma unroll
    for (int i = 0; i < 4; i++)
        pb[i] = *(const float4*)(B + (size_t)(bk + i * 8) * ldb + n0 + bnq * 4);
    #pragma unroll
    for (int i = 0; i < 2; i++) {
        As[akq * 4 + 0][arow + i * 32] = pa[i].x;
        As[akq * 4 + 1][arow + i * 32] = pa[i].y;
        As[akq * 4 + 2][arow + i * 32] = pa[i].z;
        As[akq * 4 + 3][arow + i * 32] = pa[i].w;
    }
    #pragma unroll
    for (int i = 0; i < 4; i++)
        *(float4*)&Bs[bk + i * 8][bnq * 4] = pb[i];
    __syncthreads();

    for (int k0 = 0; k0 < 256; k0 += 32) {
        const bool has_next = (k0 + 32) < 256;
        if (has_next) {   // issue next slab's gmem loads before compute
            #pragma unroll
            for (int i = 0; i < 2; i++)
                pa[i] = *(const float4*)(A + (size_t)(row0 + arow + i * 32) * 256 + k0 + 32 + akq * 4);
            #pragma unroll
            for (int i = 0; i < 4; i++)
                pb[i] = *(const float4*)(B + (size_t)(k0 + 32 + bk + i * 8) * ldb + n0 + bnq * 4);
        }
        #pragma unroll
        for (int kk = 0; kk < 32; kk++) {
            float4 av = *(const float4*)&As[kk][ty * 4];
            float4 b0 = *(const float4*)&Bs[kk][tx * 4];
            float4 b1 = *(const float4*)&Bs[kk][64 + tx * 4];
            float a[4] = {av.x, av.y, av.z, av.w};
            float b[8] = {b0.x, b0.y, b0.z, b0.w, b1.x, b1.y, b1.z, b1.w};
            #pragma unroll
            for (int i = 0; i < 4; i++)
                #pragma unroll
                for (int j = 0; j < 8; j++)
                    acc[i][j] += a[i] * b[j];
        }
        if (has_next) {
            __syncthreads();
            #pragma unroll
            for (int i = 0; i < 2; i++) {
                As[akq * 4 + 0][arow + i * 32] = pa[i].x;
                As[akq * 4 + 1][arow + i * 32] = pa[i].y;
                As[akq * 4 + 2][arow + i * 32] = pa[i].z;
                As[akq * 4 + 3][arow + i * 32] = pa[i].w;
            }
            #pragma unroll
            for (int i = 0; i < 4; i++)
                *(float4*)&Bs[bk + i * 8][bnq * 4] = pb[i];
            __syncthreads();
        }
    }

    if (MODE == 1) {
        const int ha = n0 >> 6;   // heads {ha, ha+1}
        float aAs[4], aAd[4], aBs[4], aBd[4];
        #pragma unroll
        for (int j = 0; j < 4; j++) {
            int lc = tx * 4 + j;
            aAs[j] = avec[ha * 128 + lc];
            aAd[j] = avec[ha * 128 + 64 + lc];
            aBs[j] = avec[(ha + 1) * 128 + lc];
            aBd[j] = avec[(ha + 1) * 128 + 64 + lc];
        }
        #pragma unroll
        for (int i = 0; i < 4; i++) {
            const int row = row0 + ty * 4 + i;
            __nv_bfloat162* d0 = (__nv_bfloat162*)(g_Whb + (size_t)row * DCAT + n0 + tx * 4);
            __nv_bfloat162* d1 = (__nv_bfloat162*)(g_Whb + (size_t)row * DCAT + n0 + 64 + tx * 4);
            d0[0] = __floats2bfloat162_rn(acc[i][0], acc[i][1]);
            d0[1] = __floats2bfloat162_rn(acc[i][2], acc[i][3]);
            d1[0] = __floats2bfloat162_rn(acc[i][4], acc[i][5]);
            d1[1] = __floats2bfloat162_rn(acc[i][6], acc[i][7]);
            float sA = 0.f, dA = 0.f, sB = 0.f, dB = 0.f;
            #pragma unroll
            for (int j = 0; j < 4; j++) {
                sA += acc[i][j] * aAs[j];
                dA += acc[i][j] * aAd[j];
                sB += acc[i][4 + j] * aBs[j];
                dB += acc[i][4 + j] * aBd[j];
            }
            #pragma unroll
            for (int o = 1; o < 16; o <<= 1) {
                sA += __shfl_xor_sync(~0u, sA, o);
                dA += __shfl_xor_sync(~0u, dA, o);
                sB += __shfl_xor_sync(~0u, sB, o);
                dB += __shfl_xor_sync(~0u, dB, o);
            }
            if (tx == 0) {
                g_f1s[row * 4 + ha]     = sA;
                g_f1d[row * 4 + ha]     = dA;
                g_f1s[row * 4 + ha + 1] = sB;
                g_f1d[row * 4 + ha + 1] = dB;
            }
        }
    } else {
        float as0[4], ad0[4], as1[4], ad1[4];
        #pragma unroll
        for (int j = 0; j < 4; j++) {
            int c0 = tx * 4 + j;
            int c1 = 64 + tx * 4 + j;
            as0[j] = avec[c0];
            ad0[j] = avec[NCLASS + c0];
            as1[j] = (c1 < NCLASS) ? avec[c1] : 0.f;
            ad1[j] = (c1 < NCLASS) ? avec[NCLASS + c1] : 0.f;
        }
        #pragma unroll
        for (int i = 0; i < 4; i++) {
            const int row = row0 + ty * 4 + i;
            __nv_bfloat162* e0 = (__nv_bfloat162*)(g_Wh2b + (size_t)row * 128 + tx * 4);
            __nv_bfloat162* e1 = (__nv_bfloat162*)(g_Wh2b + (size_t)row * 128 + 64 + tx * 4);
            e0[0] = __floats2bfloat162_rn(acc[i][0], acc[i][1]);
            e0[1] = __floats2bfloat162_rn(acc[i][2], acc[i][3]);
            e1[0] = __floats2bfloat162_rn(acc[i][4], acc[i][5]);
            e1[1] = __floats2bfloat162_rn(acc[i][6], acc[i][7]);
            float s = 0.f, d = 0.f;
            #pragma unroll
            for (int j = 0; j < 4; j++) {
                s += acc[i][j] * as0[j] + acc[i][4 + j] * as1[j];
                d += acc[i][j] * ad0[j] + acc[i][4 + j] * ad1[j];
            }
            #pragma unroll
            for (int o = 1; o < 16; o <<= 1) {
                s += __shfl_xor_sync(~0u, s, o);
                d += __shfl_xor_sync(~0u, d, o);
            }
            if (tx == 0) { g_fs2[row] = s; g_fd2[row] = d; }
        }
    }
}

// ---------------- K1: layer1 sparse attention + aggregation (1 block / row) ----------------
// Phase A: 8 independent LDG.128 -> per-thread nibble word (MLP=8). No-max softmax.
__global__ void __launch_bounds__(256) k1_attn(const float* __restrict__ adj) {
    const int i = blockIdx.x;
    const int t = threadIdx.x;
    const int lane = t & 31, warp = t >> 5;

    __shared__ int    s_nbr[CAP];        // byte offsets into g_Whb (j*512)
    __shared__ float4 s_p4[CAP];         // per-neighbor 4-head exp weights
    __shared__ int    s_wcnt[8];
    __shared__ float  s_wred[8][NHEADS];
    __shared__ float  s_sum[NHEADS];
    __shared__ float4 s_part[4][64];

    // ---- Phase A: stream adj row; thread t covers elements {it*1024 + t*4 + c} ----
    const float4* arow4 = (const float4*)(adj + (size_t)i * N);
    unsigned nm = 0;
    #pragma unroll
    for (int it = 0; it < 8; it++) {
        float4 v = __ldcs(&arow4[it * 256 + t]);   // independent addresses: full MLP
        unsigned pm = (v.x != 0.f ? 1u : 0u) | (v.y != 0.f ? 2u : 0u)
                    | (v.z != 0.f ? 4u : 0u) | (v.w != 0.f ? 8u : 0u);
        nm |= pm << (it * 4);
    }
    int c  = __popc(nm);
    int sc = c;
    #pragma unroll
    for (int o = 1; o < 32; o <<= 1) {
        int u = __shfl_up_sync(~0u, sc, o);
        if (lane >= o) sc += u;
    }
    if (lane == 31) s_wcnt[warp] = sc;
    __syncthreads();
    int base = sc - c, total = 0;
    #pragma unroll
    for (int k = 0; k < 8; k++) {
        int cc = s_wcnt[k];
        if (k < warp) base += cc;
        total += cc;
    }
    const int nn = min(total, CAP);
    {   // bit p of nm -> element (p>>2)*1024 + t*4 + (p&3)
        unsigned w = nm;
        int pos = base;
        while (w) {
            int p = __ffs(w) - 1;
            w &= w - 1;
            if (pos < CAP) {
                int j = ((p >> 2) << 10) + t * 4 + (p & 3);
                s_nbr[pos] = j << 9;               // byte offset: j * DCAT * 2
                g_nbr[(size_t)i * CAP + pos] = j;
            }
            pos++;
        }
    }
    if (t == 0) g_cnt[i] = nn;
    __syncthreads();

    // ---- Phase B: p = exp(lrelu(fs+fd)) one pass, accumulate sums ----
    const float4 fs4 = *(const float4*)(g_f1s + 4 * i);
    float sl[NHEADS] = {0.f, 0.f, 0.f, 0.f};
    for (int jl = t; jl < nn; jl += 256) {
        int jb = s_nbr[jl];
        const float4 fd = *(const float4*)((const char*)g_f1d + (jb >> 5));  // j*16 B
        float4 e;
        e.x = fs4.x + fd.x; e.x = e.x > 0.f ? e.x : 0.2f * e.x; e.x = __expf(e.x);
        e.y = fs4.y + fd.y; e.y = e.y > 0.f ? e.y : 0.2f * e.y; e.y = __expf(e.y);
        e.z = fs4.z + fd.z; e.z = e.z > 0.f ? e.z : 0.2f * e.z; e.z = __expf(e.z);
        e.w = fs4.w + fd.w; e.w = e.w > 0.f ? e.w : 0.2f * e.w; e.w = __expf(e.w);
        s_p4[jl] = e;
        sl[0] += e.x; sl[1] += e.y; sl[2] += e.z; sl[3] += e.w;
    }
    #pragma unroll
    for (int h = 0; h < NHEADS; h++)
        #pragma unroll
        for (int o = 16; o; o >>= 1)
            sl[h] += __shfl_xor_sync(~0u, sl[h], o);
    if (lane == 0)
        #pragma unroll
        for (int h = 0; h < NHEADS; h++) s_wred[warp][h] = sl[h];
    __syncthreads();
    if (t < NHEADS) {
        float s = 0.f;
        #pragma unroll
        for (int w2 = 0; w2 < 8; w2++) s += s_wred[w2][t];
        s_sum[t] = s;
    }
    __syncthreads();

    // ---- aggregation: 4 neighbor-groups x 64 dim-quads; LDG.64 bf16x4 ----
    const int d4 = t & 63, grp = t >> 6;
    const int h = d4 >> 4;
    const char* basep = (const char*)g_Whb + 8 * d4;
    float4 a0 = {0.f, 0.f, 0.f, 0.f}, a1 = {0.f, 0.f, 0.f, 0.f};
    {
        int jl = grp;
        for (; jl + 4 < nn; jl += 8) {
            float w0 = ((const float*)&s_p4[jl])[h];
            float w1 = ((const float*)&s_p4[jl + 4])[h];
            uint2 q0 = *(const uint2*)(basep + s_nbr[jl]);
            uint2 q1 = *(const uint2*)(basep + s_nbr[jl + 4]);
            float2 l0 = __bfloat1622float2(*(const __nv_bfloat162*)&q0.x);
            float2 h0 = __bfloat1622float2(*(const __nv_bfloat162*)&q0.y);
            float2 l1 = __bfloat1622float2(*(const __nv_bfloat162*)&q1.x);
            float2 h1 = __bfloat1622float2(*(const __nv_bfloat162*)&q1.y);
            a0.x += w0 * l0.x; a0.y += w0 * l0.y; a0.z += w0 * h0.x; a0.w += w0 * h0.y;
            a1.x += w1 * l1.x; a1.y += w1 * l1.y; a1.z += w1 * h1.x; a1.w += w1 * h1.y;
        }
        for (; jl < nn; jl += 4) {
            float w0 = ((const float*)&s_p4[jl])[h];
            uint2 q0 = *(const uint2*)(basep + s_nbr[jl]);
            float2 l0 = __bfloat1622float2(*(const __nv_bfloat162*)&q0.x);
            float2 h0 = __bfloat1622float2(*(const __nv_bfloat162*)&q0.y);
            a0.x += w0 * l0.x; a0.y += w0 * l0.y; a0.z += w0 * h0.x; a0.w += w0 * h0.y;
        }
    }
    s_part[grp][d4] = make_float4(a0.x + a1.x, a0.y + a1.y, a0.z + a1.z, a0.w + a1.w);
    __syncthreads();
    if (t < 64) {
        float4 r0 = s_part[0][t], r1 = s_part[1][t], r2 = s_part[2][t], r3 = s_part[3][t];
        float inv = 1.f / s_sum[t >> 4];
        float4 v;
        v.x = (r0.x + r1.x + r2.x + r3.x) * inv;
        v.y = (r0.y + r1.y + r2.y + r3.y) * inv;
        v.z = (r0.z + r1.z + r2.z + r3.z) * inv;
        v.w = (r0.w + r1.w + r2.w + r3.w) * inv;
        v.x = v.x > 0.f ? v.x : expm1f(v.x);
        v.y = v.y > 0.f ? v.y : expm1f(v.y);
        v.z = v.z > 0.f ? v.z : expm1f(v.z);
        v.w = v.w > 0.f ? v.w : expm1f(v.w);
        *(float4*)(g_h1 + (size_t)i * DCAT + 4 * t) = v;
    }
}

// ---------------- K3: output-layer attention (1 block / row, reuses CSR) ----------------
__global__ void __launch_bounds__(256) k3_attn(float* __restrict__ out) {
    const int i = blockIdx.x;
    const int t = threadIdx.x;
    const int lane = t & 31, warp = t >> 5;
    __shared__ int    s_nbr[CAP];      // byte offsets into g_Wh2b (j*256)
    __shared__ float  s_p[CAP];
    __shared__ float  s_red[8];
    __shared__ float  s_s;
    __shared__ float4 s_part[8][32];

    const int nn = g_cnt[i];
    const int* nb = g_nbr + (size_t)i * CAP;
    for (int jl = t; jl < nn; jl += 256) s_nbr[jl] = nb[jl] << 8;
    __syncthreads();

    const float fs = g_fs2[i];
    float sloc = 0.f;
    for (int jl = t; jl < nn; jl += 256) {
        int jb = s_nbr[jl];
        float fd = *(const float*)((const char*)g_fd2 + (jb >> 6));   // j*4 B
        float e = fs + fd;
        e = e > 0.f ? e : 0.2f * e;
        e = __expf(e);
        s_p[jl] = e;
        sloc += e;
    }
    #pragma unroll
    for (int o = 16; o; o >>= 1) sloc += __shfl_xor_sync(~0u, sloc, o);
    if (!lane) s_red[warp] = sloc;
    __syncthreads();
    if (t == 0) {
        float s = 0.f;
        #pragma unroll
        for (int w = 0; w < 8; w++) s += s_red[w];
        s_s = s;
    }
    __syncthreads();

    // gather: 8 neighbor-groups x 32 dim-quads; LDG.64 bf16x4
    const int d4 = t & 31, grp = t >> 5;
    const char* basep = (const char*)g_Wh2b + 8 * d4;
    float4 a0 = {0.f, 0.f, 0.f, 0.f}, a1 = {0.f, 0.f, 0.f, 0.f};
    {
        int jl = grp;
        for (; jl + 8 < nn; jl += 16) {
            float w0 = s_p[jl], w1 = s_p[jl + 8];
            uint2 q0 = *(const uint2*)(basep + s_nbr[jl]);
            uint2 q1 = *(const uint2*)(basep + s_nbr[jl + 8]);
            float2 l0 = __bfloat1622float2(*(const __nv_bfloat162*)&q0.x);
            float2 h0 = __bfloat1622float2(*(const __nv_bfloat162*)&q0.y);
            float2 l1 = __bfloat1622float2(*(const __nv_bfloat162*)&q1.x);
            float2 h1 = __bfloat1622float2(*(const __nv_bfloat162*)&q1.y);
            a0.x += w0 * l0.x; a0.y += w0 * l0.y; a0.z += w0 * h0.x; a0.w += w0 * h0.y;
            a1.x += w1 * l1.x; a1.y += w1 * l1.y; a1.z += w1 * h1.x; a1.w += w1 * h1.y;
        }
        for (; jl < nn; jl += 8) {
            float w0 = s_p[jl];
            uint2 q0 = *(const uint2*)(basep + s_nbr[jl]);
            float2 l0 = __bfloat1622float2(*(const __nv_bfloat162*)&q0.x);
            float2 h0 = __bfloat1622float2(*(const __nv_bfloat162*)&q0.y);
            a0.x += w0 * l0.x; a0.y += w0 * l0.y; a0.z += w0 * h0.x; a0.w += w0 * h0.y;
        }
    }
    s_part[grp][d4] = make_float4(a0.x + a1.x, a0.y + a1.y, a0.z + a1.z, a0.w + a1.w);
    __syncthreads();
    if (t < 32) {
        float4 v = {0.f, 0.f, 0.f, 0.f};
        #pragma unroll
        for (int g = 0; g < 8; g++) {
            float4 r = s_part[g][t];
            v.x += r.x; v.y += r.y; v.z += r.z; v.w += r.w;
        }
        float inv = 1.f / s_s;
        int c0 = 4 * t;
        if (c0 + 0 < NCLASS) out[(size_t)i * NCLASS + c0 + 0] = v.x * inv;
        if (c0 + 1 < NCLASS) out[(size_t)i * NCLASS + c0 + 1] = v.y * inv;
        if (c0 + 2 < NCLASS) out[(size_t)i * NCLASS + c0 + 2] = v.z * inv;
        if (c0 + 3 < NCLASS) out[(size_t)i * NCLASS + c0 + 3] = v.w * inv;
    }
}

// ---------------- launcher ----------------
extern "C" void kernel_launch(void* const* d_in, const int* in_sizes, int n_in,
                              void* d_out, int out_size) {
    const float* x       = (const float*)d_in[0];
    const float* adj     = (const float*)d_in[1];
    const float* Ws      = (const float*)d_in[2];
    const float* a_heads = (const float*)d_in[3];
    const float* W_out   = (const float*)d_in[4];
    const float* a_out   = (const float*)d_in[5];
    float* out = (float*)d_out;

    float* pB1;  cudaGetSymbolAddress((void**)&pB1, g_B1);
    float* pB2;  cudaGetSymbolAddress((void**)&pB2, g_B2);
    float* pH1;  cudaGetSymbolAddress((void**)&pH1, g_h1);

    pack_B1<<<256, 256>>>(Ws);
    pack_B2<<<128, 256>>>(W_out);
    gemm_fused<1><<<dim3(N / 64, 2), 256>>>(x, pB1, 256, a_heads);    // layer1 Wh + f1
    k1_attn<<<N, 256>>>(adj);
    gemm_fused<2><<<dim3(N / 64, 1), 256>>>(pH1, pB2, 128, a_out);    // layer2 Wh + f2
    k3_attn<<<N, 256>>>(out);
}

// round 12
// speedup vs baseline: 1.3798x; 1.1711x over previous
#include <cuda_runtime.h>
#include <cuda_bf16.h>
#include <math.h>

#define N      8192
#define NFEAT  256
#define NHID   64
#define NHEADS 4
#define NCLASS 121
#define DCAT   256   // NHEADS*NHID
#define CAP    768   // max neighbors per row (mean ~82, sigma ~9)

// ---------------- scratch (static __device__, no allocs) ----------------
__device__ __align__(16) __nv_bfloat16 g_Whb[(size_t)N * DCAT];  // layer1 Wh (bf16 gather operand)
__device__ __align__(16) float g_f1s[(size_t)N * NHEADS];  // f_src layer1, [row][head]
__device__ __align__(16) float g_f1d[(size_t)N * NHEADS];  // f_dst layer1, [row][head]
__device__ __align__(16) float g_h1[(size_t)N * DCAT];     // layer1 output (h_cat)
__device__ __align__(16) __nv_bfloat16 g_Wh2b[(size_t)N * 128];  // layer2 Wh (bf16, padded)
__device__ float g_fs2[N];
__device__ float g_fd2[N];
__device__ int   g_nbr[(size_t)N * CAP];                   // CSR neighbor lists (raw indices)
__device__ int   g_cnt[N];
__device__ __align__(16) float g_B2[256 * 128];            // packed+padded W_out [K][128]

// ---------------- weight prepack (layer2 only; layer1 reads Ws directly) ----------------
__global__ void pack_B2(const float* __restrict__ W_out) {
    int idx = blockIdx.x * blockDim.x + threadIdx.x;      // 32768
    int k = idx >> 7, n = idx & 127;
    g_B2[idx] = (n < NCLASS) ? W_out[(size_t)k * NCLASS + n] : 0.f;
}

__device__ __forceinline__ float4 cvt_tf32_4(float4 v) {
    asm("cvt.rna.tf32.f32 %0, %0;" : "+f"(v.x));
    asm("cvt.rna.tf32.f32 %0, %0;" : "+f"(v.y));
    asm("cvt.rna.tf32.f32 %0, %0;" : "+f"(v.z));
    asm("cvt.rna.tf32.f32 %0, %0;" : "+f"(v.w));
    return v;
}

// ---------------- TF32 tensor-core GEMM + f-score epilogue ----------------
// Block: 256 thr = 8 warps (warpM = w>>2 in {0,1}, warpN = w&3). Tile M=64, N=128, Kchunk=32.
// Each warp: 32x32 subtile = 2(mi) x 4(ni) m16n8k8 mma's.
// MODE 1: A=x, B from Ws (head-indexed); writes g_Whb bf16 + f1s/f1d (2 heads per block).
// MODE 2: A=g_h1, B=g_B2; writes g_Wh2b bf16 + fs2/fd2.
template <int MODE>
__global__ void __launch_bounds__(256) gemm_tc(const float* __restrict__ A,
                                               const float* __restrict__ Wsrc,
                                               const float* __restrict__ avec) {
    __shared__ float As[32][72];    // [k][row]; stride 72 -> frag loads conflict-free
    __shared__ float Bs[32][136];   // [k][n];   stride 136 -> frag loads conflict-free
    __shared__ float s_ep[4][64];
    __shared__ float d_ep[4][64];
    const int t = threadIdx.x;
    const int lane = t & 31, w = t >> 5;
    const int g = lane >> 2, t4 = lane & 3;
    const int warpM = w >> 2, warpN = w & 3;
    const int row0 = blockIdx.x * 64;
    const int n0   = (MODE == 1) ? blockIdx.y * 128 : 0;
    const int arow = t >> 3, akq = t & 7;     // A staging coords
    const int bk   = t >> 5, bnq = t & 31;    // B staging coords

    float acc[2][4][4] = {};
    float4 pa[2], pb[4];

    // ---- prologue: load + store k-slab 0 ----
    #pragma unroll
    for (int i = 0; i < 2; i++)
        pa[i] = cvt_tf32_4(*(const float4*)(A + (size_t)(row0 + arow + i * 32) * 256 + akq * 4));
    #pragma unroll
    for (int i = 0; i < 4; i++) {
        int kr = bk + i * 8;
        if (MODE == 1) {
            int n = n0 + bnq * 4, h = n >> 6, c = n & 63;
            pb[i] = cvt_tf32_4(*(const float4*)(Wsrc + ((size_t)h * 256 + kr) * 64 + c));
        } else {
            pb[i] = cvt_tf32_4(*(const float4*)(Wsrc + (size_t)kr * 128 + bnq * 4));
        }
    }
    #pragma unroll
    for (int i = 0; i < 2; i++) {
        As[akq * 4 + 0][arow + i * 32] = pa[i].x;
        As[akq * 4 + 1][arow + i * 32] = pa[i].y;
        As[akq * 4 + 2][arow + i * 32] = pa[i].z;
        As[akq * 4 + 3][arow + i * 32] = pa[i].w;
    }
    #pragma unroll
    for (int i = 0; i < 4; i++)
        *(float4*)&Bs[bk + i * 8][bnq * 4] = pb[i];
    __syncthreads();

    for (int k0 = 0; k0 < 256; k0 += 32) {
        const bool has_next = (k0 + 32) < 256;
        if (has_next) {
            #pragma unroll
            for (int i = 0; i < 2; i++)
                pa[i] = cvt_tf32_4(*(const float4*)(A + (size_t)(row0 + arow + i * 32) * 256 + k0 + 32 + akq * 4));
            #pragma unroll
            for (int i = 0; i < 4; i++) {
                int kr = k0 + 32 + bk + i * 8;
                if (MODE == 1) {
                    int n = n0 + bnq * 4, h = n >> 6, c = n & 63;
                    pb[i] = cvt_tf32_4(*(const float4*)(Wsrc + ((size_t)h * 256 + kr) * 64 + c));
                } else {
                    pb[i] = cvt_tf32_4(*(const float4*)(Wsrc + (size_t)kr * 128 + bnq * 4));
                }
            }
        }
        #pragma unroll
        for (int ks = 0; ks < 32; ks += 8) {
            float a[2][4];
            #pragma unroll
            for (int mi = 0; mi < 2; mi++) {
                int r = warpM * 32 + mi * 16;
                a[mi][0] = As[ks + t4]    [r + g];
                a[mi][1] = As[ks + t4]    [r + g + 8];
                a[mi][2] = As[ks + t4 + 4][r + g];
                a[mi][3] = As[ks + t4 + 4][r + g + 8];
            }
            #pragma unroll
            for (int ni = 0; ni < 4; ni++) {
                int nc = warpN * 32 + ni * 8 + g;
                float b0 = Bs[ks + t4][nc];
                float b1 = Bs[ks + t4 + 4][nc];
                #pragma unroll
                for (int mi = 0; mi < 2; mi++) {
                    asm volatile(
                        "mma.sync.aligned.m16n8k8.row.col.f32.tf32.tf32.f32 "
                        "{%0,%1,%2,%3}, {%4,%5,%6,%7}, {%8,%9}, {%0,%1,%2,%3};\n"
                        : "+f"(acc[mi][ni][0]), "+f"(acc[mi][ni][1]),
                          "+f"(acc[mi][ni][2]), "+f"(acc[mi][ni][3])
                        : "r"(__float_as_uint(a[mi][0])), "r"(__float_as_uint(a[mi][1])),
                          "r"(__float_as_uint(a[mi][2])), "r"(__float_as_uint(a[mi][3])),
                          "r"(__float_as_uint(b0)), "r"(__float_as_uint(b1)));
                }
            }
        }
        if (has_next) {
            __syncthreads();
            #pragma unroll
            for (int i = 0; i < 2; i++) {
                As[akq * 4 + 0][arow + i * 32] = pa[i].x;
                As[akq * 4 + 1][arow + i * 32] = pa[i].y;
                As[akq * 4 + 2][arow + i * 32] = pa[i].z;
                As[akq * 4 + 3][arow + i * 32] = pa[i].w;
            }
            #pragma unroll
            for (int i = 0; i < 4; i++)
                *(float4*)&Bs[bk + i * 8][bnq * 4] = pb[i];
            __syncthreads();
        }
    }

    // ---- epilogue: bf16 value stores + f-score reduction ----
    // Thread owns cols cl(ni,j) = warpN*32 + ni*8 + 2*t4 + j, rows rl(mi,half) = warpM*32+mi*16+half*8+g.
    float cs[8], cd[8];
    #pragma unroll
    for (int ni = 0; ni < 4; ni++)
        #pragma unroll
        for (int j = 0; j < 2; j++) {
            int cl = warpN * 32 + ni * 8 + 2 * t4 + j;
            if (MODE == 1) {
                int hl = cl >> 6, ch = cl & 63;
                int ha = (n0 >> 6) + hl;
                cs[ni * 2 + j] = avec[ha * 128 + ch];
                cd[ni * 2 + j] = avec[ha * 128 + 64 + ch];
            } else {
                cs[ni * 2 + j] = (cl < NCLASS) ? avec[cl] : 0.f;
                cd[ni * 2 + j] = (cl < NCLASS) ? avec[NCLASS + cl] : 0.f;
            }
        }
    #pragma unroll
    for (int mi = 0; mi < 2; mi++) {
        #pragma unroll
        for (int half = 0; half < 2; half++) {
            int rl = warpM * 32 + mi * 16 + half * 8 + g;
            int row = row0 + rl;
            float s = 0.f, d = 0.f;
            #pragma unroll
            for (int ni = 0; ni < 4; ni++) {
                float v0 = acc[mi][ni][half * 2 + 0];
                float v1 = acc[mi][ni][half * 2 + 1];
                s += v0 * cs[ni * 2] + v1 * cs[ni * 2 + 1];
                d += v0 * cd[ni * 2] + v1 * cd[ni * 2 + 1];
                int cl = warpN * 32 + ni * 8 + 2 * t4;
                if (MODE == 1)
                    *(__nv_bfloat162*)(g_Whb + (size_t)row * DCAT + n0 + cl) =
                        __floats2bfloat162_rn(v0, v1);
                else
                    *(__nv_bfloat162*)(g_Wh2b + (size_t)row * 128 + cl) =
                        __floats2bfloat162_rn(v0, v1);
            }
            s += __shfl_xor_sync(~0u, s, 1); s += __shfl_xor_sync(~0u, s, 2);
            d += __shfl_xor_sync(~0u, d, 1); d += __shfl_xor_sync(~0u, d, 2);
            if (t4 == 0) { s_ep[warpN][rl] = s; d_ep[warpN][rl] = d; }
        }
    }
    __syncthreads();
    if (t < 64) {
        int row = row0 + t;
        if (MODE == 1) {
            int ha = n0 >> 6;
            g_f1s[row * 4 + ha]     = s_ep[0][t] + s_ep[1][t];
            g_f1d[row * 4 + ha]     = d_ep[0][t] + d_ep[1][t];
            g_f1s[row * 4 + ha + 1] = s_ep[2][t] + s_ep[3][t];
            g_f1d[row * 4 + ha + 1] = d_ep[2][t] + d_ep[3][t];
        } else {
            g_fs2[row] = (s_ep[0][t] + s_ep[1][t]) + (s_ep[2][t] + s_ep[3][t]);
            g_fd2[row] = (d_ep[0][t] + d_ep[1][t]) + (d_ep[2][t] + d_ep[3][t]);
        }
    }
}

// ---------------- K1: layer1 sparse attention + aggregation (1 block / row) ----------------
// Phase A: 8 independent LDG.128 -> per-thread nibble word (MLP=8). No-max softmax.
__global__ void __launch_bounds__(256) k1_attn(const float* __restrict__ adj) {
    const int i = blockIdx.x;
    const int t = threadIdx.x;
    const int lane = t & 31, warp = t >> 5;

    __shared__ int    s_nbr[CAP];        // byte offsets into g_Whb (j*512)
    __shared__ float4 s_p4[CAP];         // per-neighbor 4-head exp weights
    __shared__ int    s_wcnt[8];
    __shared__ float  s_wred[8][NHEADS];
    __shared__ float  s_sum[NHEADS];
    __shared__ float4 s_part[4][64];

    // ---- Phase A: stream adj row; thread t covers elements {it*1024 + t*4 + c} ----
    const float4* arow4 = (const float4*)(adj + (size_t)i * N);
    unsigned nm = 0;
    #pragma unroll
    for (int it = 0; it < 8; it++) {
        float4 v = __ldcs(&arow4[it * 256 + t]);   // independent addresses: full MLP
        unsigned pm = (v.x != 0.f ? 1u : 0u) | (v.y != 0.f ? 2u : 0u)
                    | (v.z != 0.f ? 4u : 0u) | (v.w != 0.f ? 8u : 0u);
        nm |= pm << (it * 4);
    }
    int c  = __popc(nm);
    int sc = c;
    #pragma unroll
    for (int o = 1; o < 32; o <<= 1) {
        int u = __shfl_up_sync(~0u, sc, o);
        if (lane >= o) sc += u;
    }
    if (lane == 31) s_wcnt[warp] = sc;
    __syncthreads();
    int base = sc - c, total = 0;
    #pragma unroll
    for (int k = 0; k < 8; k++) {
        int cc = s_wcnt[k];
        if (k < warp) base += cc;
        total += cc;
    }
    const int nn = min(total, CAP);
    {   // bit p of nm -> element (p>>2)*1024 + t*4 + (p&3)
        unsigned w = nm;
        int pos = base;
        while (w) {
            int p = __ffs(w) - 1;
            w &= w - 1;
            if (pos < CAP) {
                int j = ((p >> 2) << 10) + t * 4 + (p & 3);
                s_nbr[pos] = j << 9;               // byte offset: j * DCAT * 2
                g_nbr[(size_t)i * CAP + pos] = j;
            }
            pos++;
        }
    }
    if (t == 0) g_cnt[i] = nn;
    __syncthreads();

    // ---- Phase B: p = exp(lrelu(fs+fd)) one pass, accumulate sums ----
    const float4 fs4 = *(const float4*)(g_f1s + 4 * i);
    float sl[NHEADS] = {0.f, 0.f, 0.f, 0.f};
    for (int jl = t; jl < nn; jl += 256) {
        int jb = s_nbr[jl];
        const float4 fd = *(const float4*)((const char*)g_f1d + (jb >> 5));  // j*16 B
        float4 e;
        e.x = fs4.x + fd.x; e.x = e.x > 0.f ? e.x : 0.2f * e.x; e.x = __expf(e.x);
        e.y = fs4.y + fd.y; e.y = e.y > 0.f ? e.y : 0.2f * e.y; e.y = __expf(e.y);
        e.z = fs4.z + fd.z; e.z = e.z > 0.f ? e.z : 0.2f * e.z; e.z = __expf(e.z);
        e.w = fs4.w + fd.w; e.w = e.w > 0.f ? e.w : 0.2f * e.w; e.w = __expf(e.w);
        s_p4[jl] = e;
        sl[0] += e.x; sl[1] += e.y; sl[2] += e.z; sl[3] += e.w;
    }
    #pragma unroll
    for (int h = 0; h < NHEADS; h++)
        #pragma unroll
        for (int o = 16; o; o >>= 1)
            sl[h] += __shfl_xor_sync(~0u, sl[h], o);
    if (lane == 0)
        #pragma unroll
        for (int h = 0; h < NHEADS; h++) s_wred[warp][h] = sl[h];
    __syncthreads();
    if (t < NHEADS) {
        float s = 0.f;
        #pragma unroll
        for (int w2 = 0; w2 < 8; w2++) s += s_wred[w2][t];
        s_sum[t] = s;
    }
    __syncthreads();

    // ---- aggregation: 4 neighbor-groups x 64 dim-quads; LDG.64 bf16x4 ----
    const int d4 = t & 63, grp = t >> 6;
    const int h = d4 >> 4;
    const char* basep = (const char*)g_Whb + 8 * d4;
    float4 a0 = {0.f, 0.f, 0.f, 0.f}, a1 = {0.f, 0.f, 0.f, 0.f};
    {
        int jl = grp;
        for (; jl + 4 < nn; jl += 8) {
            float w0 = ((const float*)&s_p4[jl])[h];
            float w1 = ((const float*)&s_p4[jl + 4])[h];
            uint2 q0 = *(const uint2*)(basep + s_nbr[jl]);
            uint2 q1 = *(const uint2*)(basep + s_nbr[jl + 4]);
            float2 l0 = __bfloat1622float2(*(const __nv_bfloat162*)&q0.x);
            float2 h0 = __bfloat1622float2(*(const __nv_bfloat162*)&q0.y);
            float2 l1 = __bfloat1622float2(*(const __nv_bfloat162*)&q1.x);
            float2 h1 = __bfloat1622float2(*(const __nv_bfloat162*)&q1.y);
            a0.x += w0 * l0.x; a0.y += w0 * l0.y; a0.z += w0 * h0.x; a0.w += w0 * h0.y;
            a1.x += w1 * l1.x; a1.y += w1 * l1.y; a1.z += w1 * h1.x; a1.w += w1 * h1.y;
        }
        for (; jl < nn; jl += 4) {
            float w0 = ((const float*)&s_p4[jl])[h];
            uint2 q0 = *(const uint2*)(basep + s_nbr[jl]);
            float2 l0 = __bfloat1622float2(*(const __nv_bfloat162*)&q0.x);
            float2 h0 = __bfloat1622float2(*(const __nv_bfloat162*)&q0.y);
            a0.x += w0 * l0.x; a0.y += w0 * l0.y; a0.z += w0 * h0.x; a0.w += w0 * h0.y;
        }
    }
    s_part[grp][d4] = make_float4(a0.x + a1.x, a0.y + a1.y, a0.z + a1.z, a0.w + a1.w);
    __syncthreads();
    if (t < 64) {
        float4 r0 = s_part[0][t], r1 = s_part[1][t], r2 = s_part[2][t], r3 = s_part[3][t];
        float inv = 1.f / s_sum[t >> 4];
        float4 v;
        v.x = (r0.x + r1.x + r2.x + r3.x) * inv;
        v.y = (r0.y + r1.y + r2.y + r3.y) * inv;
        v.z = (r0.z + r1.z + r2.z + r3.z) * inv;
        v.w = (r0.w + r1.w + r2.w + r3.w) * inv;
        v.x = v.x > 0.f ? v.x : expm1f(v.x);
        v.y = v.y > 0.f ? v.y : expm1f(v.y);
        v.z = v.z > 0.f ? v.z : expm1f(v.z);
        v.w = v.w > 0.f ? v.w : expm1f(v.w);
        *(float4*)(g_h1 + (size_t)i * DCAT + 4 * t) = v;
    }
}

// ---------------- K3: output-layer attention (1 block / row, reuses CSR) ----------------
__global__ void __launch_bounds__(256) k3_attn(float* __restrict__ out) {
    const int i = blockIdx.x;
    const int t = threadIdx.x;
    const int lane = t & 31, warp = t >> 5;
    __shared__ int    s_nbr[CAP];      // byte offsets into g_Wh2b (j*256)
    __shared__ float  s_p[CAP];
    __shared__ float  s_red[8];
    __shared__ float  s_s;
    __shared__ float4 s_part[8][32];

    const int nn = g_cnt[i];
    const int* nb = g_nbr + (size_t)i * CAP;
    for (int jl = t; jl < nn; jl += 256) s_nbr[jl] = nb[jl] << 8;
    __syncthreads();

    const float fs = g_fs2[i];
    float sloc = 0.f;
    for (int jl = t; jl < nn; jl += 256) {
        int jb = s_nbr[jl];
        float fd = *(const float*)((const char*)g_fd2 + (jb >> 6));   // j*4 B
        float e = fs + fd;
        e = e > 0.f ? e : 0.2f * e;
        e = __expf(e);
        s_p[jl] = e;
        sloc += e;
    }
    #pragma unroll
    for (int o = 16; o; o >>= 1) sloc += __shfl_xor_sync(~0u, sloc, o);
    if (!lane) s_red[warp] = sloc;
    __syncthreads();
    if (t == 0) {
        float s = 0.f;
        #pragma unroll
        for (int w = 0; w < 8; w++) s += s_red[w];
        s_s = s;
    }
    __syncthreads();

    // gather: 8 neighbor-groups x 32 dim-quads; LDG.64 bf16x4
    const int d4 = t & 31, grp = t >> 5;
    const char* basep = (const char*)g_Wh2b + 8 * d4;
    float4 a0 = {0.f, 0.f, 0.f, 0.f}, a1 = {0.f, 0.f, 0.f, 0.f};
    {
        int jl = grp;
        for (; jl + 8 < nn; jl += 16) {
            float w0 = s_p[jl], w1 = s_p[jl + 8];
            uint2 q0 = *(const uint2*)(basep + s_nbr[jl]);
            uint2 q1 = *(const uint2*)(basep + s_nbr[jl + 8]);
            float2 l0 = __bfloat1622float2(*(const __nv_bfloat162*)&q0.x);
            float2 h0 = __bfloat1622float2(*(const __nv_bfloat162*)&q0.y);
            float2 l1 = __bfloat1622float2(*(const __nv_bfloat162*)&q1.x);
            float2 h1 = __bfloat1622float2(*(const __nv_bfloat162*)&q1.y);
            a0.x += w0 * l0.x; a0.y += w0 * l0.y; a0.z += w0 * h0.x; a0.w += w0 * h0.y;
            a1.x += w1 * l1.x; a1.y += w1 * l1.y; a1.z += w1 * h1.x; a1.w += w1 * h1.y;
        }
        for (; jl < nn; jl += 8) {
            float w0 = s_p[jl];
            uint2 q0 = *(const uint2*)(basep + s_nbr[jl]);
            float2 l0 = __bfloat1622float2(*(const __nv_bfloat162*)&q0.x);
            float2 h0 = __bfloat1622float2(*(const __nv_bfloat162*)&q0.y);
            a0.x += w0 * l0.x; a0.y += w0 * l0.y; a0.z += w0 * h0.x; a0.w += w0 * h0.y;
        }
    }
    s_part[grp][d4] = make_float4(a0.x + a1.x, a0.y + a1.y, a0.z + a1.z, a0.w + a1.w);
    __syncthreads();
    if (t < 32) {
        float4 v = {0.f, 0.f, 0.f, 0.f};
        #pragma unroll
        for (int g = 0; g < 8; g++) {
            float4 r = s_part[g][t];
            v.x += r.x; v.y += r.y; v.z += r.z; v.w += r.w;
        }
        float inv = 1.f / s_s;
        int c0 = 4 * t;
        if (c0 + 0 < NCLASS) out[(size_t)i * NCLASS + c0 + 0] = v.x * inv;
        if (c0 + 1 < NCLASS) out[(size_t)i * NCLASS + c0 + 1] = v.y * inv;
        if (c0 + 2 < NCLASS) out[(size_t)i * NCLASS + c0 + 2] = v.z * inv;
        if (c0 + 3 < NCLASS) out[(size_t)i * NCLASS + c0 + 3] = v.w * inv;
    }
}

// ---------------- launcher ----------------
extern "C" void kernel_launch(void* const* d_in, const int* in_sizes, int n_in,
                              void* d_out, int out_size) {
    const float* x       = (const float*)d_in[0];
    const float* adj     = (const float*)d_in[1];
    const float* Ws      = (const float*)d_in[2];
    const float* a_heads = (const float*)d_in[3];
    const float* W_out   = (const float*)d_in[4];
    const float* a_out   = (const float*)d_in[5];
    float* out = (float*)d_out;

    float* pB2;  cudaGetSymbolAddress((void**)&pB2, g_B2);
    float* pH1;  cudaGetSymbolAddress((void**)&pH1, g_h1);

    pack_B2<<<128, 256>>>(W_out);
    gemm_tc<1><<<dim3(N / 64, 2), 256>>>(x, Ws, a_heads);     // layer1 Wh + f1 (TC tf32)
    k1_attn<<<N, 256>>>(adj);
    gemm_tc<2><<<dim3(N / 64, 1), 256>>>(pH1, pB2, a_out);    // layer2 Wh + f2 (TC tf32)
    k3_attn<<<N, 256>>>(out);
}